// round 5
// baseline (speedup 1.0000x reference)
#include <cuda_runtime.h>
#include <cstdint>

#define BB 2
#define DE 128
#define DO 256
#define TT 16
#define HH 64
#define WW 64
#define HREF 32
#define WREF 32
#define NBLK 16384   // TT * HREF * WREF
#define NCOLS 1024   // HREF * WREF
#define KSEL 32
#define KK 8
#define NCHUNK 32
#define CHUNK 512    // NBLK / NCHUNK

// ------------------- device scratch (touched ONLY from device code) --------
__device__ float g_in_b [(size_t)BB * NBLK * 4 * DE];   // blockified m_in
__device__ float g_out_b[(size_t)BB * NBLK * 4 * DO];   // blockified m_out
__device__ float g_pval[(size_t)BB * NCOLS * NCHUNK * KSEL];
__device__ int   g_pidx[(size_t)BB * NCOLS * NCHUNK * KSEL];
__device__ int   g_sel [(size_t)BB * NCOLS * KSEL];
__device__ float g_oidx[(size_t)BB * NCOLS * KK];
__device__ float g_oval[(size_t)BB * NCOLS * KK];

// ---- blockify [B,D,T,H,W] -> [B, n=t*1024+hb*32+wb, pos=i*2+j, D] ---------
// Destination global selected by template param INSIDE device code (the
// previous rounds' bug was passing the __device__ symbol from host).
template<int D, int NCH, bool IS_IN>
__global__ void blockify_k(const float* __restrict__ src) {
    float* __restrict__ dst = IS_IN ? g_in_b : g_out_b;
    __shared__ float tile[128][65];
    const int h  = blockIdx.x;           // 0..63
    const int t  = blockIdx.y;           // 0..15
    const int zc = blockIdx.z;           // 0 .. BB*NCH-1
    const int b  = zc / NCH;
    const int c0 = (zc % NCH) * 128;
    const int tid = threadIdx.x;         // 256 threads

    // load 128 channels x 64 w values, coalesced along w
    {
        const int w = tid & 63, cr = tid >> 6;           // cr in 0..3
        const float* base = src
            + (size_t)b * D * (TT * HH * WW)
            + (size_t)c0 * (TT * HH * WW)
            + (size_t)t * (HH * WW)
            + (size_t)h * WW;
        for (int c = cr; c < 128; c += 4)
            tile[c][w] = base[(size_t)c * (TT * HH * WW) + w];
    }
    __syncthreads();

    // write: channels contiguous in dst
    const int hb = h >> 1, ii = h & 1;
    const int c = tid & 127, half = tid >> 7;            // half in {0,1}
    const size_t blk_base = (size_t)b * NBLK + (size_t)t * (HREF * WREF) + (size_t)hb * WREF;
    for (int m = half; m < 64; m += 2) {                 // m = w coordinate
        const int wb = m >> 1, jj = m & 1;
        const size_t o = ((blk_base + wb) * 4 + (ii * 2 + jj)) * (size_t)D + c0 + c;
        dst[o] = tile[c][m];
    }
}

// priority: (value desc, index asc) — matches jax.lax.top_k tie-breaking
__device__ __forceinline__ bool beats(float av, int ai, float bv, int bi) {
    return (av > bv) || (av == bv && ai < bi);
}

// ---- per (column, row-chunk) top-32; thread-per-column, coalesced ---------
// grid (NCOLS/256, NCHUNK, BB), block 256
__global__ void topk_partial_k(const float* __restrict__ qk) {
    const int tid = threadIdx.x;
    const int j = blockIdx.x * 256 + tid;           // column 0..1023
    const int chunk = blockIdx.y;
    const int b = blockIdx.z;
    const float* col = qk + (size_t)b * NBLK * NCOLS + (size_t)chunk * CHUNK * NCOLS + j;

    float vals[KSEL];
    int   idxs[KSEL];
#pragma unroll
    for (int e = 0; e < KSEL; e++) { vals[e] = -1e30f; idxs[e] = 0x7fffffff; }
    float minv = -1e30f; int minp = 0;
    const int rbase = chunk * CHUNK;

    for (int i0 = 0; i0 < CHUNK; i0 += 8) {
        float vv[8];
#pragma unroll
        for (int u = 0; u < 8; u++) vv[u] = col[(size_t)(i0 + u) * NCOLS];
#pragma unroll
        for (int u = 0; u < 8; u++) {
            const float v = vv[u];
            if (v > minv) {
                vals[minp] = v; idxs[minp] = rbase + i0 + u;
                float mv = vals[0]; int mp = 0; int mi = idxs[0];
#pragma unroll
                for (int e = 1; e < KSEL; e++) {
                    const float ve = vals[e]; const int ie = idxs[e];
                    if (ve < mv || (ve == mv && ie > mi)) { mv = ve; mp = e; mi = ie; }
                }
                minv = mv; minp = mp;
            }
        }
    }
    const size_t base = ((size_t)(b * NCOLS + j) * NCHUNK + chunk) * KSEL;
#pragma unroll
    for (int e = 0; e < KSEL; e++) { g_pval[base + e] = vals[e]; g_pidx[base + e] = idxs[e]; }
}

// ---- merge 32x32 candidates -> exact top-32; stage results in globals -----
// grid (NCOLS, BB), block 256
__global__ void topk_merge_k() {
    __shared__ float sv[1024];
    __shared__ int   si[1024];
    __shared__ int   sel[KSEL];
    const int tid = threadIdx.x;
    const int colq = blockIdx.x, b = blockIdx.y;
    const size_t base = (size_t)(b * NCOLS + colq) * (NCHUNK * KSEL);
    for (int e = tid; e < 1024; e += 256) { sv[e] = g_pval[base + e]; si[e] = g_pidx[base + e]; }
    __syncthreads();

    // bitonic sort descending by (value desc, index asc)
    for (int k = 2; k <= 1024; k <<= 1) {
        for (int jj = k >> 1; jj > 0; jj >>= 1) {
            for (int t = tid; t < 1024; t += 256) {
                const int ixj = t ^ jj;
                if (ixj > t) {
                    float av = sv[t], bv = sv[ixj];
                    int   ai = si[t], bi = si[ixj];
                    const bool desc = ((t & k) == 0);
                    const bool sw = desc ? beats(bv, bi, av, ai) : beats(av, ai, bv, bi);
                    if (sw) { sv[t] = bv; sv[ixj] = av; si[t] = bi; si[ixj] = ai; }
                }
            }
            __syncthreads();
        }
    }

    if (tid < KK) {
        g_oval[(size_t)(b * NCOLS + colq) * KK + tid] = sv[tid];
        g_oidx[(size_t)(b * NCOLS + colq) * KK + tid] = (float)si[tid];
    }
    if (tid < KSEL) sel[tid] = si[tid];
    __syncthreads();
    if (tid == 0) {   // ascending index order (reference gathers ascending)
        for (int a = 1; a < KSEL; a++) {
            const int v = sel[a]; int p = a - 1;
            while (p >= 0 && sel[p] > v) { sel[p + 1] = sel[p]; p--; }
            sel[p + 1] = v;
        }
    }
    __syncthreads();
    if (tid < KSEL) g_sel[(size_t)(b * NCOLS + colq) * KSEL + tid] = sel[tid];
}

// ---- attention: one CTA per (b, query block); writes output 0 -------------
// grid (BB*NCOLS), block 256
__global__ void attention_k(const float* __restrict__ q_in, float* __restrict__ out) {
    __shared__ float q_s[4][128];
    __shared__ float p_s[4][128];
    __shared__ float kbuf[512];    // m_in block  [pos][c], 4x128
    __shared__ float vbuf[1024];   // m_out block [pos][c], 4x256
    __shared__ int   sel[KSEL];

    const int tid = threadIdx.x;
    const int b = blockIdx.x >> 10;
    const int colq = blockIdx.x & 1023;
    const int hr = colq >> 5, wr = colq & 31;

    if (tid < KSEL) {
        int n = g_sel[(size_t)(b * NCOLS + colq) * KSEL + tid];
        if (n < 0) n = 0;
        if (n >= NBLK) n = NBLK - 1;   // defensive clamp
        sel[tid] = n;
    }

    // load + pre-scale q: 4 queries x 128 channels
    {
        const int c = tid & 127, ii = tid >> 7;
        const size_t qoff = ((size_t)(b * DE + c) * HH + (2 * hr + ii)) * WW + 2 * wr;
        const float v0 = q_in[qoff], v1 = q_in[qoff + 1];
        const float sc = 0.08838834764831845f;   // 1/sqrt(128)
        q_s[ii * 2 + 0][c] = v0 * sc;
        q_s[ii * 2 + 1][c] = v1 * sc;
    }
    __syncthreads();

    // QK: 16 dot products (4 q x 4 pos), 16 lanes per dot
    const int grp = tid >> 4, sub = tid & 15;
    const int ql = grp >> 2, pl = grp & 3;
    for (int slot = 0; slot < KSEL; slot++) {
        const int n = sel[slot];
        if (tid < 128)
            ((float4*)kbuf)[tid] = ((const float4*)g_in_b)[((size_t)(b * NBLK + n)) * 128 + tid];
        __syncthreads();
        float part = 0.f;
        const float* kv = &kbuf[pl * 128];
        const float* qv = &q_s[ql][0];
#pragma unroll
        for (int c = sub; c < 128; c += 16) part += kv[c] * qv[c];
        part += __shfl_xor_sync(0xffffffffu, part, 8);
        part += __shfl_xor_sync(0xffffffffu, part, 4);
        part += __shfl_xor_sync(0xffffffffu, part, 2);
        part += __shfl_xor_sync(0xffffffffu, part, 1);
        if (sub == 0) p_s[ql][slot * 4 + pl] = part;
        __syncthreads();
    }

    // softmax over 128 keys; one warp per query
    {
        const int w = tid >> 5, lane = tid & 31;
        if (w < 4) {
            float v0 = p_s[w][lane],      v1 = p_s[w][lane + 32];
            float v2 = p_s[w][lane + 64], v3 = p_s[w][lane + 96];
            float m = fmaxf(fmaxf(v0, v1), fmaxf(v2, v3));
#pragma unroll
            for (int o = 16; o; o >>= 1) m = fmaxf(m, __shfl_xor_sync(0xffffffffu, m, o));
            float e0 = __expf(v0 - m), e1 = __expf(v1 - m);
            float e2 = __expf(v2 - m), e3 = __expf(v3 - m);
            float s = e0 + e1 + e2 + e3;
#pragma unroll
            for (int o = 16; o; o >>= 1) s += __shfl_xor_sync(0xffffffffu, s, o);
            const float inv = __fdividef(1.f, s);
            p_s[w][lane]      = e0 * inv; p_s[w][lane + 32] = e1 * inv;
            p_s[w][lane + 64] = e2 * inv; p_s[w][lane + 96] = e3 * inv;
        }
    }
    __syncthreads();

    // PV: thread owns output channel c = tid (0..255)
    float a0 = 0.f, a1 = 0.f, a2 = 0.f, a3 = 0.f;
    const int c = tid;
    for (int slot = 0; slot < KSEL; slot++) {
        const int n = sel[slot];
        ((float4*)vbuf)[tid] = ((const float4*)g_out_b)[((size_t)(b * NBLK + n)) * 256 + tid];
        __syncthreads();
#pragma unroll
        for (int pos = 0; pos < 4; pos++) {
            const float v = vbuf[pos * 256 + c];
            const int pidx = slot * 4 + pos;
            a0 += v * p_s[0][pidx];
            a1 += v * p_s[1][pidx];
            a2 += v * p_s[2][pidx];
            a3 += v * p_s[3][pidx];
        }
        __syncthreads();
    }

    const size_t ob = ((size_t)(b * DO + c) * HH + 2 * hr) * WW + 2 * wr;
    out[ob]          = a0;
    out[ob + 1]      = a1;
    out[ob + WW]     = a2;
    out[ob + WW + 1] = a3;
}

// ---- final: copy staged topk idx/val into d_out tail ----------------------
__global__ void aux_write_k(float* __restrict__ out_idx, float* __restrict__ out_val) {
    const int i = blockIdx.x * 256 + threadIdx.x;   // 0 .. BB*NCOLS*KK-1
    if (i < BB * NCOLS * KK) {
        out_idx[i] = g_oidx[i];
        out_val[i] = g_oval[i];
    }
}

// ---------------------------------------------------------------------------
extern "C" void kernel_launch(void* const* d_in, const int* in_sizes, int n_in,
                              void* d_out, int out_size) {
    const float* m_in   = (const float*)d_in[0];
    const float* m_out  = (const float*)d_in[1];
    const float* q_in   = (const float*)d_in[2];
    const float* qk_ref = (const float*)d_in[3];

    float* out_mem = (float*)d_out;                          // [B,256,64,64]
    float* out_idx = out_mem + (size_t)BB * DO * HH * WW;    // [B,1024,8]
    float* out_val = out_idx + (size_t)BB * NCOLS * KK;      // [B,1024,8]

    {   // blockify (dst selected inside device code — no symbol-from-host)
        dim3 g1(HH, TT, BB * 1);
        blockify_k<DE, 1, true ><<<g1, 256>>>(m_in);
        dim3 g2(HH, TT, BB * 2);
        blockify_k<DO, 2, false><<<g2, 256>>>(m_out);
    }
    {   // top-k
        dim3 gp(NCOLS / 256, NCHUNK, BB);
        topk_partial_k<<<gp, 256>>>(qk_ref);
        dim3 gm(NCOLS, BB);
        topk_merge_k<<<gm, 256>>>();
    }
    // attention writes output 0
    attention_k<<<BB * NCOLS, 256>>>(q_in, out_mem);
    // aux outputs last
    aux_write_k<<<(BB * NCOLS * KK + 255) / 256, 256>>>(out_idx, out_val);
}

// round 6
// speedup vs baseline: 2.6122x; 2.6122x over previous
#include <cuda_runtime.h>
#include <cstdint>

#define BB 2
#define DE 128
#define DO 256
#define TT 16
#define HH 64
#define WW 64
#define HREF 32
#define WREF 32
#define NBLK 16384   // TT * HREF * WREF
#define NCOLS 1024   // HREF * WREF
#define KSEL 32
#define KK 8
#define NCHUNK 32
#define CHUNK 512    // NBLK / NCHUNK
#define CAP 64
#define NEG_INF (-1e30f)

// ------------------- device scratch (touched ONLY from device code) --------
__device__ float g_in_b [(size_t)BB * NBLK * 4 * DE];   // blockified m_in
__device__ float g_out_b[(size_t)BB * NBLK * 4 * DO];   // blockified m_out
__device__ float g_pval[(size_t)BB * NCOLS * NCHUNK * KSEL];  // sorted chunk lists
__device__ float g_cut [BB * NCOLS];                    // 32nd-largest per column
__device__ int   g_ccnt[BB * NCOLS];                    // candidate counters
__device__ float g_cval[(size_t)BB * NCOLS * CAP];
__device__ int   g_cidx[(size_t)BB * NCOLS * CAP];

// ---- blockify [B,D,T,H,W] -> [B, n=t*1024+hb*32+wb, pos=i*2+j, D] ---------
template<int D, int NCH, bool IS_IN>
__global__ void blockify_k(const float* __restrict__ src) {
    float* __restrict__ dst = IS_IN ? g_in_b : g_out_b;
    __shared__ float tile[128][65];
    const int h  = blockIdx.x;            // 0..63
    const int t  = blockIdx.y;            // 0..15
    const int zc = blockIdx.z;            // 0 .. BB*NCH-1
    const int b  = zc / NCH;
    const int c0 = (zc % NCH) * 128;
    const int tid = threadIdx.x;          // 256

    {   // load 128 channels x 64 w, coalesced along w
        const int w = tid & 63, cr = tid >> 6;
        const float* base = src
            + (size_t)b * D * (TT * HH * WW)
            + (size_t)c0 * (TT * HH * WW)
            + (size_t)t * (HH * WW)
            + (size_t)h * WW;
        for (int c = cr; c < 128; c += 4)
            tile[c][w] = base[(size_t)c * (TT * HH * WW) + w];
    }
    __syncthreads();

    const int hb = h >> 1, ii = h & 1;
    const int c = tid & 127, half = tid >> 7;
    const size_t blk_base = (size_t)b * NBLK + (size_t)t * (HREF * WREF) + (size_t)hb * WREF;
    for (int m = half; m < 64; m += 2) {
        const int wb = m >> 1, jj = m & 1;
        const size_t o = ((blk_base + wb) * 4 + (ii * 2 + jj)) * (size_t)D + c0 + c;
        dst[o] = tile[c][m];
    }
}

// ---- partial: per (column, chunk) thread; values-only sorted top-32 -------
// grid (4, NCHUNK, BB), block 256.  Strict '>' + ascending scan = jax ties.
__global__ void topk_partial_k(const float* __restrict__ qk) {
    const int tid = threadIdx.x;
    const int j = blockIdx.x * 256 + tid;
    const int chunk = blockIdx.y;
    const int b = blockIdx.z;
    const float* col = qk + (size_t)b * NBLK * NCOLS + (size_t)chunk * CHUNK * NCOLS + j;

    float vals[KSEL];                       // sorted descending
#pragma unroll
    for (int e = 0; e < KSEL; e++) vals[e] = NEG_INF;

    for (int i0 = 0; i0 < CHUNK; i0 += 8) {
        float vv[8];
#pragma unroll
        for (int u = 0; u < 8; u++) vv[u] = col[(size_t)(i0 + u) * NCOLS];
#pragma unroll
        for (int u = 0; u < 8; u++) {
            const float v = vv[u];
            if (v > vals[KSEL - 1]) {
                bool bprev = true;                   // v > vals[KSEL-1]
#pragma unroll
                for (int e = KSEL - 1; e >= 1; e--) {
                    const bool b1 = v > vals[e - 1];
                    vals[e] = b1 ? vals[e - 1] : (bprev ? v : vals[e]);
                    bprev = b1;
                }
                if (bprev) vals[0] = v;
            }
        }
    }
    const size_t base = ((size_t)(b * NCOLS + j) * NCHUNK + chunk) * KSEL;
#pragma unroll
    for (int e = 0; e < KSEL; e++) g_pval[base + e] = vals[e];
}

// ---- warp merge of two sorted-desc 32-lists (value-only), keep top-32 -----
__device__ __forceinline__ float warp_merge_desc(float a, float bfull) {
    const int lane = threadIdx.x & 31;
    const float br = __shfl_sync(0xffffffffu, bfull, 31 - lane);
    float c = fmaxf(a, br);                 // bitonic, contains top-32 of union
#pragma unroll
    for (int d = 16; d >= 1; d >>= 1) {
        const float o = __shfl_xor_sync(0xffffffffu, c, d);
        c = ((lane & d) == 0) ? fmaxf(c, o) : fminf(c, o);
    }
    return c;                               // sorted desc
}

// ---- merge: exact cut (32nd value) per column; zero counters --------------
// grid (NCOLS, BB), block 256
__global__ void topk_merge_k() {
    __shared__ float lists[8][KSEL];
    const int tid = threadIdx.x, lane = tid & 31, w = tid >> 5;
    const int colq = blockIdx.x, b = blockIdx.y;
    const size_t base = (size_t)(b * NCOLS + colq) * (NCHUNK * KSEL);

    const float a0 = g_pval[base + (4 * w + 0) * KSEL + lane];
    const float a1 = g_pval[base + (4 * w + 1) * KSEL + lane];
    const float a2 = g_pval[base + (4 * w + 2) * KSEL + lane];
    const float a3 = g_pval[base + (4 * w + 3) * KSEL + lane];
    const float m = warp_merge_desc(warp_merge_desc(a0, a1), warp_merge_desc(a2, a3));
    lists[w][lane] = m;
    __syncthreads();
    if (w == 0) {
        float acc = lists[0][lane];
#pragma unroll
        for (int s = 1; s < 8; s++) acc = warp_merge_desc(acc, lists[s][lane]);
        float cut = acc;                    // min across lanes = 32nd value
#pragma unroll
        for (int d = 16; d >= 1; d >>= 1) cut = fminf(cut, __shfl_xor_sync(0xffffffffu, cut, d));
        if (lane == 0) { g_cut[b * NCOLS + colq] = cut; g_ccnt[b * NCOLS + colq] = 0; }
    }
}

// ---- collect: rescan, append (v,idx) with v >= cut ------------------------
// grid (4, NCHUNK, BB), block 256
__global__ void collect_k(const float* __restrict__ qk) {
    const int tid = threadIdx.x;
    const int j = blockIdx.x * 256 + tid;
    const int chunk = blockIdx.y;
    const int b = blockIdx.z;
    const int cb = b * NCOLS + j;
    const float cut = g_cut[cb];
    const float* col = qk + (size_t)b * NBLK * NCOLS + (size_t)chunk * CHUNK * NCOLS + j;

    for (int i0 = 0; i0 < CHUNK; i0 += 8) {
        float vv[8];
#pragma unroll
        for (int u = 0; u < 8; u++) vv[u] = col[(size_t)(i0 + u) * NCOLS];
#pragma unroll
        for (int u = 0; u < 8; u++) {
            if (vv[u] >= cut) {
                const int pos = atomicAdd(&g_ccnt[cb], 1);
                if (pos < CAP) {
                    g_cval[(size_t)cb * CAP + pos] = vv[u];
                    g_cidx[(size_t)cb * CAP + pos] = chunk * CHUNK + i0 + u;
                }
            }
        }
    }
}

__device__ __forceinline__ bool beats(float av, int ai, float bv, int bi) {
    return (av > bv) || (av == bv && ai < bi);
}

// ---- attention + finalize: one CTA per (b, query block) -------------------
// grid (BB*NCOLS), block 256
__global__ void attention_k(const float* __restrict__ q_in, float* __restrict__ out,
                            float* __restrict__ out_idx, float* __restrict__ out_val) {
    __shared__ float q_s[4][128];
    __shared__ float p_s[4][128];
    __shared__ float kbuf[2][512];
    __shared__ float vbuf[2][1024];
    __shared__ float cv[CAP];
    __shared__ int   ci[CAP];
    __shared__ int   sel[KSEL];

    const int tid = threadIdx.x;
    const int b = blockIdx.x >> 10;
    const int colq = blockIdx.x & 1023;
    const int hr = colq >> 5, wr = colq & 31;
    const int cb = b * NCOLS + colq;

    // stage candidates
    if (tid < CAP) {
        int cnt = g_ccnt[cb]; if (cnt > CAP) cnt = CAP;
        if (tid < cnt) { cv[tid] = g_cval[(size_t)cb * CAP + tid]; ci[tid] = g_cidx[(size_t)cb * CAP + tid]; }
        else           { cv[tid] = NEG_INF; ci[tid] = 0x7fffffff; }
    }
    // load + pre-scale q
    {
        const int c = tid & 127, ii = tid >> 7;
        const size_t qoff = ((size_t)(b * DE + c) * HH + (2 * hr + ii)) * WW + 2 * wr;
        const float v0 = q_in[qoff], v1 = q_in[qoff + 1];
        const float sc = 0.08838834764831845f;   // 1/sqrt(128)
        q_s[ii * 2 + 0][c] = v0 * sc;
        q_s[ii * 2 + 1][c] = v1 * sc;
    }
    __syncthreads();

    // warp 0: bitonic sort of 64 candidates, desc by (v desc, idx asc)
    if (tid < 32) {
        for (int k = 2; k <= CAP; k <<= 1) {
            for (int jj = k >> 1; jj > 0; jj >>= 1) {
#pragma unroll
                for (int t = tid; t < CAP; t += 32) {
                    const int ixj = t ^ jj;
                    if (ixj > t) {
                        float av = cv[t], bv = cv[ixj];
                        int   ai = ci[t], bi = ci[ixj];
                        const bool desc = ((t & k) == 0);
                        const bool sw = desc ? beats(bv, bi, av, ai) : beats(av, ai, bv, bi);
                        if (sw) { cv[t] = bv; cv[ixj] = av; ci[t] = bi; ci[ixj] = ai; }
                    }
                }
                __syncwarp();
            }
        }
    }
    __syncthreads();
    if (tid < KSEL) sel[tid] = ci[tid];
    if (tid < KK) {
        out_val[cb * KK + tid] = cv[tid];
        out_idx[cb * KK + tid] = (float)ci[tid];
    }
    __syncthreads();

    // QK: double-buffered gather of 4x128 key blocks
    const int grp = tid >> 4, sub = tid & 15;
    const int ql = grp >> 2, pl = grp & 3;
    float4 nk;
    if (tid < 128)
        nk = ((const float4*)g_in_b)[((size_t)(b * NBLK + sel[0])) * 128 + tid];
    for (int slot = 0; slot < KSEL; slot++) {
        const int buf = slot & 1;
        if (tid < 128) ((float4*)kbuf[buf])[tid] = nk;
        __syncthreads();
        if (tid < 128 && slot + 1 < KSEL)
            nk = ((const float4*)g_in_b)[((size_t)(b * NBLK + sel[slot + 1])) * 128 + tid];
        float part = 0.f;
        const float* kv = &kbuf[buf][pl * 128];
        const float* qv = &q_s[ql][0];
#pragma unroll
        for (int c = sub; c < 128; c += 16) part += kv[c] * qv[c];
        part += __shfl_xor_sync(0xffffffffu, part, 8);
        part += __shfl_xor_sync(0xffffffffu, part, 4);
        part += __shfl_xor_sync(0xffffffffu, part, 2);
        part += __shfl_xor_sync(0xffffffffu, part, 1);
        if (sub == 0) p_s[ql][slot * 4 + pl] = part;
    }
    __syncthreads();

    // prefetch first V block (overlaps softmax)
    float4 nv = ((const float4*)g_out_b)[((size_t)(b * NBLK + sel[0])) * 256 + tid];

    // softmax over 128 keys; one warp per query
    {
        const int w = tid >> 5, lane = tid & 31;
        if (w < 4) {
            float v0 = p_s[w][lane],      v1 = p_s[w][lane + 32];
            float v2 = p_s[w][lane + 64], v3 = p_s[w][lane + 96];
            float m = fmaxf(fmaxf(v0, v1), fmaxf(v2, v3));
#pragma unroll
            for (int o = 16; o; o >>= 1) m = fmaxf(m, __shfl_xor_sync(0xffffffffu, m, o));
            float e0 = __expf(v0 - m), e1 = __expf(v1 - m);
            float e2 = __expf(v2 - m), e3 = __expf(v3 - m);
            float s = e0 + e1 + e2 + e3;
#pragma unroll
            for (int o = 16; o; o >>= 1) s += __shfl_xor_sync(0xffffffffu, s, o);
            const float inv = __fdividef(1.f, s);
            p_s[w][lane]      = e0 * inv; p_s[w][lane + 32] = e1 * inv;
            p_s[w][lane + 64] = e2 * inv; p_s[w][lane + 96] = e3 * inv;
        }
    }
    __syncthreads();

    // PV: double-buffered gather of 4x256 value blocks; thread owns channel
    float a0 = 0.f, a1 = 0.f, a2 = 0.f, a3 = 0.f;
    for (int slot = 0; slot < KSEL; slot++) {
        const int buf = slot & 1;
        ((float4*)vbuf[buf])[tid] = nv;
        __syncthreads();
        if (slot + 1 < KSEL)
            nv = ((const float4*)g_out_b)[((size_t)(b * NBLK + sel[slot + 1])) * 256 + tid];
#pragma unroll
        for (int pos = 0; pos < 4; pos++) {
            const float v = vbuf[buf][pos * 256 + tid];
            const int pidx = slot * 4 + pos;
            a0 += v * p_s[0][pidx];
            a1 += v * p_s[1][pidx];
            a2 += v * p_s[2][pidx];
            a3 += v * p_s[3][pidx];
        }
    }

    const size_t ob = ((size_t)(b * DO + tid) * HH + 2 * hr) * WW + 2 * wr;
    *(float2*)(out + ob)      = make_float2(a0, a1);
    *(float2*)(out + ob + WW) = make_float2(a2, a3);
}

// ---------------------------------------------------------------------------
extern "C" void kernel_launch(void* const* d_in, const int* in_sizes, int n_in,
                              void* d_out, int out_size) {
    const float* m_in   = (const float*)d_in[0];
    const float* m_out  = (const float*)d_in[1];
    const float* q_in   = (const float*)d_in[2];
    const float* qk_ref = (const float*)d_in[3];

    float* out_mem = (float*)d_out;                          // [B,256,64,64]
    float* out_idx = out_mem + (size_t)BB * DO * HH * WW;    // [B,1024,8]
    float* out_val = out_idx + (size_t)BB * NCOLS * KK;      // [B,1024,8]

    {   // blockify
        dim3 g1(HH, TT, BB * 1);
        blockify_k<DE, 1, true ><<<g1, 256>>>(m_in);
        dim3 g2(HH, TT, BB * 2);
        blockify_k<DO, 2, false><<<g2, 256>>>(m_out);
    }
    {   // selection
        dim3 gp(NCOLS / 256, NCHUNK, BB);
        topk_partial_k<<<gp, 256>>>(qk_ref);
        dim3 gm(NCOLS, BB);
        topk_merge_k<<<gm, 256>>>();
        collect_k<<<gp, 256>>>(qk_ref);
    }
    // attention (+finalize, writes all three outputs)
    attention_k<<<BB * NCOLS, 256>>>(q_in, out_mem, out_idx, out_val);
}

// round 7
// speedup vs baseline: 3.9677x; 1.5189x over previous
#include <cuda_runtime.h>
#include <cstdint>

#define BB 2
#define DE 128
#define DO 256
#define TT 16
#define HH 64
#define WW 64
#define HREF 32
#define WREF 32
#define NBLK 16384   // TT * HREF * WREF
#define NCOLS 1024   // HREF * WREF
#define KSEL 32
#define KK 8
#define NCHUNK 32
#define CHUNK 512    // NBLK / NCHUNK
#define LSZ 4        // per-chunk candidate list size
#define CAP 128
#define NEG_INF (-1e30f)

// ------------------- device scratch (touched ONLY from device code) --------
__device__ float g_in_b [(size_t)BB * NBLK * 4 * DE];
__device__ float g_out_b[(size_t)BB * NBLK * 4 * DO];
__device__ float4 g_pval4[(size_t)BB * NCOLS * NCHUNK];   // per-chunk sorted top-4
__device__ float g_cut [BB * NCOLS];
__device__ int   g_ccnt[BB * NCOLS];
__device__ float g_cval[(size_t)BB * NCOLS * CAP];
__device__ int   g_cidx[(size_t)BB * NCOLS * CAP];

// ---------------------------- cp.async helpers -----------------------------
__device__ __forceinline__ void cp16(void* smem_dst, const void* gmem_src) {
    unsigned sa = (unsigned)__cvta_generic_to_shared(smem_dst);
    asm volatile("cp.async.cg.shared.global [%0], [%1], 16;\n" :: "r"(sa), "l"(gmem_src));
}
__device__ __forceinline__ void cp_commit() { asm volatile("cp.async.commit_group;\n"); }
template<int N> __device__ __forceinline__ void cp_wait() {
    asm volatile("cp.async.wait_group %0;\n" :: "n"(N));
}

// ---- blockify [B,D,T,H,W] -> [B, n=t*1024+hb*32+wb, pos=i*2+j, D] ---------
template<int D, int NCH, bool IS_IN>
__global__ void blockify_k(const float* __restrict__ src) {
    float* __restrict__ dst = IS_IN ? g_in_b : g_out_b;
    __shared__ float tile[128][65];
    const int h  = blockIdx.x;
    const int t  = blockIdx.y;
    const int zc = blockIdx.z;
    const int b  = zc / NCH;
    const int c0 = (zc % NCH) * 128;
    const int tid = threadIdx.x;

    {
        const int w = tid & 63, cr = tid >> 6;
        const float* base = src
            + (size_t)b * D * (TT * HH * WW)
            + (size_t)c0 * (TT * HH * WW)
            + (size_t)t * (HH * WW)
            + (size_t)h * WW;
        for (int c = cr; c < 128; c += 4)
            tile[c][w] = base[(size_t)c * (TT * HH * WW) + w];
    }
    __syncthreads();

    const int hb = h >> 1, ii = h & 1;
    const int c = tid & 127, half = tid >> 7;
    const size_t blk_base = (size_t)b * NBLK + (size_t)t * (HREF * WREF) + (size_t)hb * WREF;
    for (int m = half; m < 64; m += 2) {
        const int wb = m >> 1, jj = m & 1;
        const size_t o = ((blk_base + wb) * 4 + (ii * 2 + jj)) * (size_t)D + c0 + c;
        dst[o] = tile[c][m];
    }
}

// ---- partial: per (column, chunk) thread; register top-4 ------------------
// grid (4, NCHUNK, BB), block 256
__global__ void topk_partial_k(const float* __restrict__ qk) {
    const int tid = threadIdx.x;
    const int j = blockIdx.x * 256 + tid;
    const int chunk = blockIdx.y;
    const int b = blockIdx.z;
    const float* col = qk + (size_t)b * NBLK * NCOLS + (size_t)chunk * CHUNK * NCOLS + j;

    float v0 = NEG_INF, v1 = NEG_INF, v2 = NEG_INF, v3 = NEG_INF;  // desc

    for (int i0 = 0; i0 < CHUNK; i0 += 16) {
        float vv[16];
#pragma unroll
        for (int u = 0; u < 16; u++) vv[u] = col[(size_t)(i0 + u) * NCOLS];
#pragma unroll
        for (int u = 0; u < 16; u++) {
            const float v = vv[u];
            if (v > v3) {
                const float o0 = v0, o1 = v1, o2 = v2;
                const bool b0 = v > o0, b1 = v > o1, b2 = v > o2;
                v3 = b2 ? o2 : v;
                v2 = b1 ? o1 : (b2 ? v : o2);
                v1 = b0 ? o0 : (b1 ? v : o1);
                v0 = b0 ? v  : o0;
            }
        }
    }
    g_pval4[(size_t)(b * NCOLS + j) * NCHUNK + chunk] = make_float4(v0, v1, v2, v3);
}

// ---- warp sort / merge (desc) ---------------------------------------------
__device__ __forceinline__ float wsort_desc(float c) {
    const int lane = threadIdx.x & 31;
#pragma unroll
    for (int k = 2; k <= 32; k <<= 1)
#pragma unroll
        for (int d = k >> 1; d; d >>= 1) {
            const float o = __shfl_xor_sync(0xffffffffu, c, d);
            const bool keepmax = (((lane & d) == 0) == ((lane & k) == 0));
            c = keepmax ? fmaxf(c, o) : fminf(c, o);
        }
    return c;
}
__device__ __forceinline__ float wmerge_desc(float a, float bfull) {
    const int lane = threadIdx.x & 31;
    const float br = __shfl_sync(0xffffffffu, bfull, 31 - lane);
    float c = fmaxf(a, br);
#pragma unroll
    for (int d = 16; d >= 1; d >>= 1) {
        const float o = __shfl_xor_sync(0xffffffffu, c, d);
        c = ((lane & d) == 0) ? fmaxf(c, o) : fminf(c, o);
    }
    return c;
}

// ---- merge: cut = 32nd largest of the 128 merged candidates ---------------
// grid (NCOLS/8, BB), block 256 (8 warps, 1 column each)
__global__ void topk_merge_k() {
    const int tid = threadIdx.x, lane = tid & 31, w = tid >> 5;
    const int col = blockIdx.x * 8 + w, b = blockIdx.y;
    const float4 v = g_pval4[(size_t)(b * NCOLS + col) * NCHUNK + lane];
    float s = wsort_desc(v.x);
    s = wmerge_desc(s, wsort_desc(v.y));
    s = wmerge_desc(s, wsort_desc(v.z));
    s = wmerge_desc(s, wsort_desc(v.w));
    const float cut = __shfl_sync(0xffffffffu, s, 31);
    if (lane == 0) { g_cut[b * NCOLS + col] = cut; g_ccnt[b * NCOLS + col] = 0; }
}

// ---- collect: rescan, append (v,idx) with v >= cut ------------------------
// grid (4, NCHUNK, BB), block 256
__global__ void collect_k(const float* __restrict__ qk) {
    const int tid = threadIdx.x;
    const int j = blockIdx.x * 256 + tid;
    const int chunk = blockIdx.y;
    const int b = blockIdx.z;
    const int cb = b * NCOLS + j;
    const float cut = g_cut[cb];
    const float* col = qk + (size_t)b * NBLK * NCOLS + (size_t)chunk * CHUNK * NCOLS + j;

    for (int i0 = 0; i0 < CHUNK; i0 += 16) {
        float vv[16];
#pragma unroll
        for (int u = 0; u < 16; u++) vv[u] = col[(size_t)(i0 + u) * NCOLS];
#pragma unroll
        for (int u = 0; u < 16; u++) {
            if (vv[u] >= cut) {
                const int pos = atomicAdd(&g_ccnt[cb], 1);
                if (pos < CAP) {
                    g_cval[(size_t)cb * CAP + pos] = vv[u];
                    g_cidx[(size_t)cb * CAP + pos] = chunk * CHUNK + i0 + u;
                }
            }
        }
    }
}

__device__ __forceinline__ bool beats(float av, int ai, float bv, int bi) {
    return (av > bv) || (av == bv && ai < bi);
}

// ---- attention + finalize: one CTA per (b, query block) -------------------
// grid (BB*NCOLS), block 256
__global__ void __launch_bounds__(256) attention_k(
        const float* __restrict__ q_in, float* __restrict__ out,
        float* __restrict__ out_idx, float* __restrict__ out_val) {
    __shared__ float q_s[4][128];
    __shared__ float p_s[4][128];
    __shared__ float kbuf[8][512];     // 8-deep K ring (2KB slots)
    __shared__ float vbuf[4][1024];    // 4-deep V ring (4KB slots)
    __shared__ float cv[CAP];
    __shared__ int   ci[CAP];
    __shared__ int   sel[KSEL];

    const int tid = threadIdx.x;
    const int b = blockIdx.x >> 10;
    const int colq = blockIdx.x & 1023;
    const int hr = colq >> 5, wr = colq & 31;
    const int cb = b * NCOLS + colq;

    // stage candidates
    if (tid < CAP) {
        int cnt = g_ccnt[cb]; if (cnt > CAP) cnt = CAP;
        if (tid < cnt) { cv[tid] = g_cval[(size_t)cb * CAP + tid]; ci[tid] = g_cidx[(size_t)cb * CAP + tid]; }
        else           { cv[tid] = NEG_INF; ci[tid] = 0x7fffffff; }
    }
    // load + pre-scale q
    {
        const int c = tid & 127, ii = tid >> 7;
        const size_t qoff = ((size_t)(b * DE + c) * HH + (2 * hr + ii)) * WW + 2 * wr;
        const float a0 = q_in[qoff], a1 = q_in[qoff + 1];
        const float sc = 0.08838834764831845f;   // 1/sqrt(128)
        q_s[ii * 2 + 0][c] = a0 * sc;
        q_s[ii * 2 + 1][c] = a1 * sc;
    }
    __syncthreads();

    // warp 0: bitonic sort of CAP candidates, desc by (v desc, idx asc)
    if (tid < 32) {
        for (int k = 2; k <= CAP; k <<= 1) {
            for (int jj = k >> 1; jj > 0; jj >>= 1) {
                for (int t = tid; t < CAP; t += 32) {
                    const int ixj = t ^ jj;
                    if (ixj > t) {
                        float av = cv[t], bv = cv[ixj];
                        int   ai = ci[t], bi = ci[ixj];
                        const bool desc = ((t & k) == 0);
                        const bool sw = desc ? beats(bv, bi, av, ai) : beats(av, ai, bv, bi);
                        if (sw) { cv[t] = bv; cv[ixj] = av; ci[t] = bi; ci[ixj] = ai; }
                    }
                }
                __syncwarp();
            }
        }
    }
    __syncthreads();
    if (tid < KSEL) sel[tid] = ci[tid];
    if (tid < KK) {
        out_val[cb * KK + tid] = cv[tid];
        out_idx[cb * KK + tid] = (float)ci[tid];
    }
    __syncthreads();

    // ---- QK phase: 8-deep cp.async ring, 7 in flight ----------------------
    const int grp = tid >> 4, sub = tid & 15;
    const int ql = grp >> 2, pl = grp & 3;
#pragma unroll
    for (int s = 0; s < 7; s++) {        // prologue: slots 0..6
        if (tid < 128)
            cp16(&kbuf[s][tid * 4],
                 (const char*)(g_in_b + ((size_t)(b * NBLK + sel[s])) * 512) + tid * 16);
        cp_commit();
    }
    for (int s = 0; s < KSEL; s++) {
        cp_wait<6>();                    // slot s complete
        __syncthreads();                 // everyone done with slot s-1's buffer too
        if (s + 7 < KSEL && tid < 128)   // refill buffer (s-1)&7 — safe after sync
            cp16(&kbuf[(s + 7) & 7][tid * 4],
                 (const char*)(g_in_b + ((size_t)(b * NBLK + sel[s + 7])) * 512) + tid * 16);
        cp_commit();
        float part = 0.f;
        const float* kv = &kbuf[s & 7][pl * 128];
        const float* qv = &q_s[ql][0];
#pragma unroll
        for (int c = sub; c < 128; c += 16) part += kv[c] * qv[c];
        part += __shfl_xor_sync(0xffffffffu, part, 8);
        part += __shfl_xor_sync(0xffffffffu, part, 4);
        part += __shfl_xor_sync(0xffffffffu, part, 2);
        part += __shfl_xor_sync(0xffffffffu, part, 1);
        if (sub == 0) p_s[ql][s * 4 + pl] = part;
    }

    // ---- V prologue (overlaps softmax): slots 0..2 ------------------------
#pragma unroll
    for (int s = 0; s < 3; s++) {
        cp16(&vbuf[s][tid * 4],
             (const char*)(g_out_b + ((size_t)(b * NBLK + sel[s])) * 1024) + tid * 16);
        cp_commit();
    }
    __syncthreads();                     // p_s fully written

    // softmax over 128 keys; one warp per query
    {
        const int w = tid >> 5, lane = tid & 31;
        if (w < 4) {
            float x0 = p_s[w][lane],      x1 = p_s[w][lane + 32];
            float x2 = p_s[w][lane + 64], x3 = p_s[w][lane + 96];
            float m = fmaxf(fmaxf(x0, x1), fmaxf(x2, x3));
#pragma unroll
            for (int o = 16; o; o >>= 1) m = fmaxf(m, __shfl_xor_sync(0xffffffffu, m, o));
            float e0 = __expf(x0 - m), e1 = __expf(x1 - m);
            float e2 = __expf(x2 - m), e3 = __expf(x3 - m);
            float ssum = e0 + e1 + e2 + e3;
#pragma unroll
            for (int o = 16; o; o >>= 1) ssum += __shfl_xor_sync(0xffffffffu, ssum, o);
            const float inv = __fdividef(1.f, ssum);
            p_s[w][lane]      = e0 * inv; p_s[w][lane + 32] = e1 * inv;
            p_s[w][lane + 64] = e2 * inv; p_s[w][lane + 96] = e3 * inv;
        }
    }
    __syncthreads();

    // ---- PV phase: 4-deep cp.async ring, 3 in flight ----------------------
    float a0 = 0.f, a1 = 0.f, a2 = 0.f, a3 = 0.f;
    for (int s = 0; s < KSEL; s++) {
        cp_wait<2>();
        __syncthreads();
        if (s + 3 < KSEL)
            cp16(&vbuf[(s + 3) & 3][tid * 4],
                 (const char*)(g_out_b + ((size_t)(b * NBLK + sel[s + 3])) * 1024) + tid * 16);
        cp_commit();
        const float* vb = vbuf[s & 3];
#pragma unroll
        for (int pos = 0; pos < 4; pos++) {
            const float v = vb[pos * 256 + tid];
            const int pidx = s * 4 + pos;
            a0 += v * p_s[0][pidx];
            a1 += v * p_s[1][pidx];
            a2 += v * p_s[2][pidx];
            a3 += v * p_s[3][pidx];
        }
    }

    const size_t ob = ((size_t)(b * DO + tid) * HH + 2 * hr) * WW + 2 * wr;
    *(float2*)(out + ob)      = make_float2(a0, a1);
    *(float2*)(out + ob + WW) = make_float2(a2, a3);
}

// ---------------------------------------------------------------------------
extern "C" void kernel_launch(void* const* d_in, const int* in_sizes, int n_in,
                              void* d_out, int out_size) {
    const float* m_in   = (const float*)d_in[0];
    const float* m_out  = (const float*)d_in[1];
    const float* q_in   = (const float*)d_in[2];
    const float* qk_ref = (const float*)d_in[3];

    float* out_mem = (float*)d_out;
    float* out_idx = out_mem + (size_t)BB * DO * HH * WW;
    float* out_val = out_idx + (size_t)BB * NCOLS * KK;

    {   // blockify
        dim3 g1(HH, TT, BB * 1);
        blockify_k<DE, 1, true ><<<g1, 256>>>(m_in);
        dim3 g2(HH, TT, BB * 2);
        blockify_k<DO, 2, false><<<g2, 256>>>(m_out);
    }
    {   // selection
        dim3 gp(NCOLS / 256, NCHUNK, BB);
        topk_partial_k<<<gp, 256>>>(qk_ref);
        dim3 gm(NCOLS / 8, BB);
        topk_merge_k<<<gm, 256>>>();
        collect_k<<<gp, 256>>>(qk_ref);
    }
    // attention (+finalize, writes all three outputs)
    attention_k<<<BB * NCOLS, 256>>>(q_in, out_mem, out_idx, out_val);
}

// round 8
// speedup vs baseline: 4.8447x; 1.2210x over previous
#include <cuda_runtime.h>
#include <cstdint>

#define BB 2
#define DE 128
#define DO 256
#define TT 16
#define HH 64
#define WW 64
#define HREF 32
#define WREF 32
#define NBLK 16384   // TT * HREF * WREF
#define NCOLS 1024   // HREF * WREF
#define KSEL 32
#define KK 8
#define NCHUNK 32
#define CHUNK 512    // NBLK / NCHUNK
#define CAPM 64      // per-column candidate cap in merge
#define NEG_INF (-1e30f)

// attention dynamic smem: kbuf 32*512 | vbuf 4*1024 | q 512 | p 512 | sel 32
#define SM_K    0
#define SM_V    16384
#define SM_Q    20480
#define SM_P    20992
#define SM_SEL  21504
#define SMEM_ATT_BYTES (21504 * 4 + 128)

// ------------------- device scratch (touched ONLY from device code) --------
__device__ float  g_in_b [(size_t)BB * NBLK * 4 * DE];
__device__ float  g_out_b[(size_t)BB * NBLK * 4 * DO];
__device__ float4 g_pval4[(size_t)BB * NCOLS * NCHUNK];   // per-chunk top-4 vals
__device__ int4   g_pidx4[(size_t)BB * NCOLS * NCHUNK];   // per-chunk top-4 idxs
__device__ int    g_sel  [(size_t)BB * NCOLS * KSEL];     // ascending-sorted top-32

// ---------------------------- cp.async helpers -----------------------------
__device__ __forceinline__ void cp16(void* smem_dst, const void* gmem_src) {
    unsigned sa = (unsigned)__cvta_generic_to_shared(smem_dst);
    asm volatile("cp.async.cg.shared.global [%0], [%1], 16;\n" :: "r"(sa), "l"(gmem_src));
}
__device__ __forceinline__ void cp4(void* smem_dst, const void* gmem_src) {
    unsigned sa = (unsigned)__cvta_generic_to_shared(smem_dst);
    asm volatile("cp.async.ca.shared.global [%0], [%1], 4;\n" :: "r"(sa), "l"(gmem_src));
}
__device__ __forceinline__ void cp_commit() { asm volatile("cp.async.commit_group;\n"); }
template<int N> __device__ __forceinline__ void cp_wait() {
    asm volatile("cp.async.wait_group %0;\n" :: "n"(N));
}

// ---- blockify [B,D,T,H,W] -> [B, n=t*1024+hb*32+wb, pos=i*2+j, D] ---------
template<int D, int NCH, bool IS_IN>
__global__ void blockify_k(const float* __restrict__ src) {
    float* __restrict__ dst = IS_IN ? g_in_b : g_out_b;
    __shared__ float tile[128][65];
    const int h  = blockIdx.x;
    const int t  = blockIdx.y;
    const int zc = blockIdx.z;
    const int b  = zc / NCH;
    const int c0 = (zc % NCH) * 128;
    const int tid = threadIdx.x;

    {
        const int w = tid & 63, cr = tid >> 6;
        const float* base = src
            + (size_t)b * D * (TT * HH * WW)
            + (size_t)c0 * (TT * HH * WW)
            + (size_t)t * (HH * WW)
            + (size_t)h * WW;
        for (int c = cr; c < 128; c += 4)
            tile[c][w] = base[(size_t)c * (TT * HH * WW) + w];
    }
    __syncthreads();

    const int hb = h >> 1, ii = h & 1;
    const int c = tid & 127, half = tid >> 7;
    const size_t blk_base = (size_t)b * NBLK + (size_t)t * (HREF * WREF) + (size_t)hb * WREF;
    for (int m = half; m < 64; m += 2) {
        const int wb = m >> 1, jj = m & 1;
        const size_t o = ((blk_base + wb) * 4 + (ii * 2 + jj)) * (size_t)D + c0 + c;
        dst[o] = tile[c][m];
    }
}

// ---- partial: per (column, chunk) thread; register top-4 (val + idx) ------
// grid (4, NCHUNK, BB), block 256
__global__ void topk_partial_k(const float* __restrict__ qk) {
    const int tid = threadIdx.x;
    const int j = blockIdx.x * 256 + tid;
    const int chunk = blockIdx.y;
    const int b = blockIdx.z;
    const float* col = qk + (size_t)b * NBLK * NCOLS + (size_t)chunk * CHUNK * NCOLS + j;

    float w0 = NEG_INF, w1 = NEG_INF, w2 = NEG_INF, w3 = NEG_INF;  // desc
    int   x0 = 0x7fffffff, x1 = 0x7fffffff, x2 = 0x7fffffff, x3 = 0x7fffffff;
    const int rbase = chunk * CHUNK;

    for (int r0 = 0; r0 < CHUNK; r0 += 16) {
        float vv[16];
#pragma unroll
        for (int u = 0; u < 16; u++) vv[u] = col[(size_t)(r0 + u) * NCOLS];
#pragma unroll
        for (int u = 0; u < 16; u++) {
            const float v = vv[u];
            if (v > w3) {                       // strict > + asc order = jax ties
                const float o0 = w0, o1 = w1, o2 = w2;
                const int   j0 = x0, j1 = x1, j2 = x2;
                const bool c0 = v > o0, c1 = v > o1, c2 = v > o2;
                const int myi = rbase + r0 + u;
                w3 = c2 ? o2 : v;            x3 = c2 ? j2 : myi;
                w2 = c1 ? o1 : (c2 ? v : o2); x2 = c1 ? j1 : (c2 ? myi : j2);
                w1 = c0 ? o0 : (c1 ? v : o1); x1 = c0 ? j0 : (c1 ? myi : j1);
                w0 = c0 ? v : o0;            x0 = c0 ? myi : j0;
            }
        }
    }
    const size_t o = (size_t)(b * NCOLS + j) * NCHUNK + chunk;
    g_pval4[o] = make_float4(w0, w1, w2, w3);
    g_pidx4[o] = make_int4(x0, x1, x2, x3);
}

// ---- warp sort / merge (desc, value-only) ---------------------------------
__device__ __forceinline__ float wsort_desc(float c) {
    const int lane = threadIdx.x & 31;
#pragma unroll
    for (int k = 2; k <= 32; k <<= 1)
#pragma unroll
        for (int d = k >> 1; d; d >>= 1) {
            const float o = __shfl_xor_sync(0xffffffffu, c, d);
            const bool keepmax = (((lane & d) == 0) == ((lane & k) == 0));
            c = keepmax ? fmaxf(c, o) : fminf(c, o);
        }
    return c;
}
__device__ __forceinline__ float wmerge_desc(float a, float bfull) {
    const int lane = threadIdx.x & 31;
    const float br = __shfl_sync(0xffffffffu, bfull, 31 - lane);
    float c = fmaxf(a, br);
#pragma unroll
    for (int d = 16; d >= 1; d >>= 1) {
        const float o = __shfl_xor_sync(0xffffffffu, c, d);
        c = ((lane & d) == 0) ? fmaxf(c, o) : fminf(c, o);
    }
    return c;
}
__device__ __forceinline__ int wsort_int_asc(int x) {
    const int lane = threadIdx.x & 31;
#pragma unroll
    for (int k = 2; k <= 32; k <<= 1)
#pragma unroll
        for (int d = k >> 1; d; d >>= 1) {
            const int o = __shfl_xor_sync(0xffffffffu, x, d);
            const bool keepmin = (((lane & d) == 0) == ((lane & k) == 0));
            x = keepmin ? min(x, o) : max(x, o);
        }
    return x;
}

__device__ __forceinline__ bool beats(float av, int ai, float bv, int bi) {
    return (av > bv) || (av == bv && ai < bi);
}

// ---- merge + finalize: exact top-32 per column, all in one kernel ---------
// grid (NCOLS/8, BB), block 256 (8 warps, 1 column each)
__global__ void topk_merge_k(const float* __restrict__ qk,
                             float* __restrict__ out_idx, float* __restrict__ out_val) {
    __shared__ float cand_v[8][CAPM];
    __shared__ int   cand_i[8][CAPM];
    __shared__ int   cnt[8];
    const int tid = threadIdx.x, lane = tid & 31, w = tid >> 5;
    const int col = blockIdx.x * 8 + w, b = blockIdx.y;
    const int cb = b * NCOLS + col;

    const size_t po = (size_t)cb * NCHUNK + lane;
    const float4 pv = g_pval4[po];
    const int4   pi = g_pidx4[po];

    // cut = 32nd largest among the 128 listed candidates (lower bound on true 32nd)
    float s = wsort_desc(pv.x);
    s = wmerge_desc(s, wsort_desc(pv.y));
    s = wmerge_desc(s, wsort_desc(pv.z));
    s = wmerge_desc(s, wsort_desc(pv.w));
    const float cut = __shfl_sync(0xffffffffu, s, 31);

    if (lane == 0) cnt[w] = 0;
    __syncwarp();

    const bool flagged = (pv.w >= cut);   // chunk may hide a 5th candidate
    if (!flagged) {
        const float fv[4] = {pv.x, pv.y, pv.z, pv.w};
        const int   fi[4] = {pi.x, pi.y, pi.z, pi.w};
#pragma unroll
        for (int e = 0; e < 4; e++)
            if (fv[e] >= cut) {
                const int pos = atomicAdd(&cnt[w], 1);
                if (pos < CAPM) { cand_v[w][pos] = fv[e]; cand_i[w][pos] = fi[e]; }
            }
    }
    unsigned mask = __ballot_sync(0xffffffffu, flagged);
    while (mask) {                        // rare: rescan flagged chunks
        const int cc = __ffs(mask) - 1; mask &= mask - 1;
        const float* colp = qk + (size_t)b * NBLK * NCOLS + (size_t)(cc * CHUNK) * NCOLS + col;
        for (int r = lane; r < CHUNK; r += 32) {
            const float v = colp[(size_t)r * NCOLS];
            if (v >= cut) {
                const int pos = atomicAdd(&cnt[w], 1);
                if (pos < CAPM) { cand_v[w][pos] = v; cand_i[w][pos] = cc * CHUNK + r; }
            }
        }
    }
    __syncwarp();
    const int n = min(cnt[w], CAPM);
    for (int t = lane; t < CAPM; t += 32)
        if (t >= n) { cand_v[w][t] = NEG_INF; cand_i[w][t] = 0x7fffffff; }
    __syncwarp();

    // bitonic sort CAPM=64, desc by (v desc, idx asc)
    for (int k = 2; k <= CAPM; k <<= 1) {
        for (int jj = k >> 1; jj > 0; jj >>= 1) {
#pragma unroll
            for (int t = lane; t < CAPM; t += 32) {
                const int ixj = t ^ jj;
                if (ixj > t) {
                    float av = cand_v[w][t], bv = cand_v[w][ixj];
                    int   ai = cand_i[w][t], bi = cand_i[w][ixj];
                    const bool desc = ((t & k) == 0);
                    const bool sw = desc ? beats(bv, bi, av, ai) : beats(av, ai, bv, bi);
                    if (sw) { cand_v[w][t] = bv; cand_v[w][ixj] = av;
                              cand_i[w][t] = bi; cand_i[w][ixj] = ai; }
                }
            }
            __syncwarp();
        }
    }

    if (lane < KK) {
        out_val[cb * KK + lane] = cand_v[w][lane];
        out_idx[cb * KK + lane] = (float)cand_i[w][lane];
    }
    // sel = top-32 indices sorted ascending (reference gathers ascending)
    const int asc = wsort_int_asc(cand_i[w][lane]);
    g_sel[(size_t)cb * KSEL + lane] = asc;
}

// ---- attention: one CTA per (b, query block); K resident, V self-ring -----
// grid (BB*NCOLS), block 256, dynamic smem
__global__ void __launch_bounds__(256) attention_k(
        const float* __restrict__ q_in, float* __restrict__ out) {
    extern __shared__ float sm[];
    float* kbuf = sm + SM_K;       // [32][512]
    float* vbuf = sm + SM_V;       // [4][1024]
    float* q_s  = sm + SM_Q;       // [4][128]
    float* p_s  = sm + SM_P;       // [4][128]
    int*   sel  = (int*)(sm + SM_SEL);

    const int tid = threadIdx.x;
    const int b = blockIdx.x >> 10;
    const int colq = blockIdx.x & 1023;
    const int hr = colq >> 5, wr = colq & 31;
    const int cb = b * NCOLS + colq;

    if (tid < KSEL) sel[tid] = g_sel[(size_t)cb * KSEL + tid];
    {   // load + pre-scale q
        const int c = tid & 127, ii = tid >> 7;
        const size_t qoff = ((size_t)(b * DE + c) * HH + (2 * hr + ii)) * WW + 2 * wr;
        const float a0 = q_in[qoff], a1 = q_in[qoff + 1];
        const float sc = 0.08838834764831845f;   // 1/sqrt(128)
        q_s[(ii * 2 + 0) * 128 + c] = a0 * sc;
        q_s[(ii * 2 + 1) * 128 + c] = a1 * sc;
    }
    __syncthreads();

    // bulk-load ALL 32 K blocks (64 KB), one commit group
    {
        const size_t gbase = (size_t)b * NBLK;
#pragma unroll
        for (int i = 0; i < 16; i++) {
            const int f4 = i * 256 + tid;          // float4 idx into 32*128
            const int slot = f4 >> 7, off = f4 & 127;
            cp16(kbuf + (size_t)f4 * 4,
                 (const float4*)g_in_b + (gbase + sel[slot]) * 128 + off);
        }
        cp_commit();
    }
    // V ring prologue: slots 0..2, SELF-CONSUMED words (pos*256+tid)
#pragma unroll
    for (int s = 0; s < 3; s++) {
        const float* src = g_out_b + ((size_t)b * NBLK + sel[s]) * 1024 + tid;
#pragma unroll
        for (int pos = 0; pos < 4; pos++)
            cp4(vbuf + s * 1024 + pos * 256 + tid, src + pos * 256);
        cp_commit();
    }
    cp_wait<3>();                  // K group done (3 V groups may be pending)
    __syncthreads();

    // QK: sync-free, q in registers
    const int grp = tid >> 4, sub = tid & 15;
    const int ql = grp >> 2, pl = grp & 3;
    float qr[8];
#pragma unroll
    for (int k = 0; k < 8; k++) qr[k] = q_s[ql * 128 + sub + 16 * k];
#pragma unroll 4
    for (int s = 0; s < KSEL; s++) {
        const float* kv = kbuf + s * 512 + pl * 128;
        float part = 0.f;
#pragma unroll
        for (int k = 0; k < 8; k++) part += qr[k] * kv[sub + 16 * k];
        part += __shfl_xor_sync(0xffffffffu, part, 8);
        part += __shfl_xor_sync(0xffffffffu, part, 4);
        part += __shfl_xor_sync(0xffffffffu, part, 2);
        part += __shfl_xor_sync(0xffffffffu, part, 1);
        if (sub == 0) p_s[ql * 128 + s * 4 + pl] = part;
    }
    __syncthreads();

    // softmax over 128 keys; one warp per query
    {
        const int w = tid >> 5, lane = tid & 31;
        if (w < 4) {
            float x0 = p_s[w * 128 + lane],      x1 = p_s[w * 128 + lane + 32];
            float x2 = p_s[w * 128 + lane + 64], x3 = p_s[w * 128 + lane + 96];
            float m = fmaxf(fmaxf(x0, x1), fmaxf(x2, x3));
#pragma unroll
            for (int o = 16; o; o >>= 1) m = fmaxf(m, __shfl_xor_sync(0xffffffffu, m, o));
            float e0 = __expf(x0 - m), e1 = __expf(x1 - m);
            float e2 = __expf(x2 - m), e3 = __expf(x3 - m);
            float ssum = e0 + e1 + e2 + e3;
#pragma unroll
            for (int o = 16; o; o >>= 1) ssum += __shfl_xor_sync(0xffffffffu, ssum, o);
            const float inv = __fdividef(1.f, ssum);
            p_s[w * 128 + lane]      = e0 * inv; p_s[w * 128 + lane + 32] = e1 * inv;
            p_s[w * 128 + lane + 64] = e2 * inv; p_s[w * 128 + lane + 96] = e3 * inv;
        }
    }
    __syncthreads();

    // PV: self-consuming ring, NO syncthreads in loop
    float a0 = 0.f, a1 = 0.f, a2 = 0.f, a3 = 0.f;
    for (int s = 0; s < KSEL; s++) {
        cp_wait<2>();              // slot s's group complete (per-thread FIFO)
        if (s + 3 < KSEL) {
            const float* src = g_out_b + ((size_t)b * NBLK + sel[s + 3]) * 1024 + tid;
#pragma unroll
            for (int pos = 0; pos < 4; pos++)
                cp4(vbuf + ((s + 3) & 3) * 1024 + pos * 256 + tid, src + pos * 256);
        }
        cp_commit();               // commit every iter (empty groups ok)
        const float* vb = vbuf + (s & 3) * 1024;
#pragma unroll
        for (int pos = 0; pos < 4; pos++) {
            const float v = vb[pos * 256 + tid];
            const int pidx = s * 4 + pos;
            a0 += v * p_s[0 * 128 + pidx];
            a1 += v * p_s[1 * 128 + pidx];
            a2 += v * p_s[2 * 128 + pidx];
            a3 += v * p_s[3 * 128 + pidx];
        }
    }

    const size_t ob = ((size_t)(b * DO + tid) * HH + 2 * hr) * WW + 2 * wr;
    *(float2*)(out + ob)      = make_float2(a0, a1);
    *(float2*)(out + ob + WW) = make_float2(a2, a3);
}

// ---------------------------------------------------------------------------
extern "C" void kernel_launch(void* const* d_in, const int* in_sizes, int n_in,
                              void* d_out, int out_size) {
    const float* m_in   = (const float*)d_in[0];
    const float* m_out  = (const float*)d_in[1];
    const float* q_in   = (const float*)d_in[2];
    const float* qk_ref = (const float*)d_in[3];

    float* out_mem = (float*)d_out;
    float* out_idx = out_mem + (size_t)BB * DO * HH * WW;
    float* out_val = out_idx + (size_t)BB * NCOLS * KK;

    {   // blockify
        dim3 g1(HH, TT, BB * 1);
        blockify_k<DE, 1, true ><<<g1, 256>>>(m_in);
        dim3 g2(HH, TT, BB * 2);
        blockify_k<DO, 2, false><<<g2, 256>>>(m_out);
    }
    {   // selection (collect pass eliminated; merge finalizes)
        dim3 gp(NCOLS / 256, NCHUNK, BB);
        topk_partial_k<<<gp, 256>>>(qk_ref);
        dim3 gm(NCOLS / 8, BB);
        topk_merge_k<<<gm, 256>>>(qk_ref, out_idx, out_val);
    }
    // attention
    cudaFuncSetAttribute(attention_k, cudaFuncAttributeMaxDynamicSharedMemorySize, SMEM_ATT_BYTES);
    attention_k<<<BB * NCOLS, 256, SMEM_ATT_BYTES>>>(q_in, out_mem);
}

// round 9
// speedup vs baseline: 5.1876x; 1.0708x over previous
#include <cuda_runtime.h>
#include <cstdint>

#define BB 2
#define DE 128
#define DO 256
#define TT 16
#define HH 64
#define WW 64
#define HREF 32
#define WREF 32
#define NBLK 16384   // TT * HREF * WREF
#define NCOLS 1024   // HREF * WREF
#define KSEL 32
#define KK 8
#define NCHUNK 32
#define CHUNK 512    // NBLK / NCHUNK
#define CAPM 64      // per-column candidate cap in merge
#define NEG_INF (-1e30f)

// attention dynamic smem (floats): kbuf 32*512 | q 512 | p 512 | sel 32
#define SM_K    0
#define SM_Q    16384
#define SM_P    16896
#define SM_SEL  17408
#define SMEM_ATT_BYTES (17440 * 4 + 128)

// ------------------- device scratch (touched ONLY from device code) --------
__device__ float  g_in_b [(size_t)BB * NBLK * 4 * DE];
__device__ float  g_out_b[(size_t)BB * NBLK * 4 * DO];
__device__ float4 g_pval4[(size_t)BB * NCOLS * NCHUNK];   // per-chunk top-4 vals
__device__ int4   g_pidx4[(size_t)BB * NCOLS * NCHUNK];   // per-chunk top-4 idxs
__device__ int    g_sel  [(size_t)BB * NCOLS * KSEL];     // ascending-sorted top-32

// ---------------------------- cp.async helpers -----------------------------
__device__ __forceinline__ void cp16(void* smem_dst, const void* gmem_src) {
    unsigned sa = (unsigned)__cvta_generic_to_shared(smem_dst);
    asm volatile("cp.async.cg.shared.global [%0], [%1], 16;\n" :: "r"(sa), "l"(gmem_src));
}
__device__ __forceinline__ void cp_commit() { asm volatile("cp.async.commit_group;\n"); }
template<int N> __device__ __forceinline__ void cp_wait() {
    asm volatile("cp.async.wait_group %0;\n" :: "n"(N));
}

// ---- blockify [B,D,T,H,W] -> [B, n=t*1024+hb*32+wb, pos=i*2+j, D] ---------
template<int D, int NCH, bool IS_IN>
__global__ void blockify_k(const float* __restrict__ src) {
    float* __restrict__ dst = IS_IN ? g_in_b : g_out_b;
    __shared__ float tile[128][65];
    const int h  = blockIdx.x;
    const int t  = blockIdx.y;
    const int zc = blockIdx.z;
    const int b  = zc / NCH;
    const int c0 = (zc % NCH) * 128;
    const int tid = threadIdx.x;

    {
        const int w = tid & 63, cr = tid >> 6;
        const float* base = src
            + (size_t)b * D * (TT * HH * WW)
            + (size_t)c0 * (TT * HH * WW)
            + (size_t)t * (HH * WW)
            + (size_t)h * WW;
        for (int c = cr; c < 128; c += 4)
            tile[c][w] = base[(size_t)c * (TT * HH * WW) + w];
    }
    __syncthreads();

    const int hb = h >> 1, ii = h & 1;
    const int c = tid & 127, half = tid >> 7;
    const size_t blk_base = (size_t)b * NBLK + (size_t)t * (HREF * WREF) + (size_t)hb * WREF;
    for (int m = half; m < 64; m += 2) {
        const int wb = m >> 1, jj = m & 1;
        const size_t o = ((blk_base + wb) * 4 + (ii * 2 + jj)) * (size_t)D + c0 + c;
        dst[o] = tile[c][m];
    }
}

// ---- partial: per (column, chunk) thread; register top-4 (val + idx) ------
// grid (4, NCHUNK, BB), block 256
__global__ void topk_partial_k(const float* __restrict__ qk) {
    const int tid = threadIdx.x;
    const int j = blockIdx.x * 256 + tid;
    const int chunk = blockIdx.y;
    const int b = blockIdx.z;
    const float* col = qk + (size_t)b * NBLK * NCOLS + (size_t)chunk * CHUNK * NCOLS + j;

    float w0 = NEG_INF, w1 = NEG_INF, w2 = NEG_INF, w3 = NEG_INF;  // desc
    int   x0 = 0x7fffffff, x1 = 0x7fffffff, x2 = 0x7fffffff, x3 = 0x7fffffff;
    const int rbase = chunk * CHUNK;

    for (int r0 = 0; r0 < CHUNK; r0 += 16) {
        float vv[16];
#pragma unroll
        for (int u = 0; u < 16; u++) vv[u] = col[(size_t)(r0 + u) * NCOLS];
#pragma unroll
        for (int u = 0; u < 16; u++) {
            const float v = vv[u];
            if (v > w3) {                       // strict > + asc order = jax ties
                const float o0 = w0, o1 = w1, o2 = w2;
                const int   j0 = x0, j1 = x1, j2 = x2;
                const bool c0 = v > o0, c1 = v > o1, c2 = v > o2;
                const int myi = rbase + r0 + u;
                w3 = c2 ? o2 : v;            x3 = c2 ? j2 : myi;
                w2 = c1 ? o1 : (c2 ? v : o2); x2 = c1 ? j1 : (c2 ? myi : j2);
                w1 = c0 ? o0 : (c1 ? v : o1); x1 = c0 ? j0 : (c1 ? myi : j1);
                w0 = c0 ? v : o0;            x0 = c0 ? myi : j0;
            }
        }
    }
    const size_t o = (size_t)(b * NCOLS + j) * NCHUNK + chunk;
    g_pval4[o] = make_float4(w0, w1, w2, w3);
    g_pidx4[o] = make_int4(x0, x1, x2, x3);
}

// ---- warp sort / merge (desc, value-only) ---------------------------------
__device__ __forceinline__ float wsort_desc(float c) {
    const int lane = threadIdx.x & 31;
#pragma unroll
    for (int k = 2; k <= 32; k <<= 1)
#pragma unroll
        for (int d = k >> 1; d; d >>= 1) {
            const float o = __shfl_xor_sync(0xffffffffu, c, d);
            const bool keepmax = (((lane & d) == 0) == ((lane & k) == 0));
            c = keepmax ? fmaxf(c, o) : fminf(c, o);
        }
    return c;
}
__device__ __forceinline__ float wmerge_desc(float a, float bfull) {
    const int lane = threadIdx.x & 31;
    const float br = __shfl_sync(0xffffffffu, bfull, 31 - lane);
    float c = fmaxf(a, br);
#pragma unroll
    for (int d = 16; d >= 1; d >>= 1) {
        const float o = __shfl_xor_sync(0xffffffffu, c, d);
        c = ((lane & d) == 0) ? fmaxf(c, o) : fminf(c, o);
    }
    return c;
}
__device__ __forceinline__ int wsort_int_asc(int x) {
    const int lane = threadIdx.x & 31;
#pragma unroll
    for (int k = 2; k <= 32; k <<= 1)
#pragma unroll
        for (int d = k >> 1; d; d >>= 1) {
            const int o = __shfl_xor_sync(0xffffffffu, x, d);
            const bool keepmin = (((lane & d) == 0) == ((lane & k) == 0));
            x = keepmin ? min(x, o) : max(x, o);
        }
    return x;
}

__device__ __forceinline__ bool beats(float av, int ai, float bv, int bi) {
    return (av > bv) || (av == bv && ai < bi);
}

// ---- merge + finalize: exact top-32 per column ----------------------------
// grid (NCOLS/8, BB), block 256 (8 warps, 1 column each)
__global__ void topk_merge_k(const float* __restrict__ qk,
                             float* __restrict__ out_idx, float* __restrict__ out_val) {
    __shared__ float cand_v[8][CAPM];
    __shared__ int   cand_i[8][CAPM];
    __shared__ int   cnt[8];
    const int tid = threadIdx.x, lane = tid & 31, w = tid >> 5;
    const int col = blockIdx.x * 8 + w, b = blockIdx.y;
    const int cb = b * NCOLS + col;

    const size_t po = (size_t)cb * NCHUNK + lane;
    const float4 pv = g_pval4[po];
    const int4   pi = g_pidx4[po];

    // cut = 32nd largest among the 128 listed candidates (lower bound on true 32nd)
    float s = wsort_desc(pv.x);
    s = wmerge_desc(s, wsort_desc(pv.y));
    s = wmerge_desc(s, wsort_desc(pv.z));
    s = wmerge_desc(s, wsort_desc(pv.w));
    const float cut = __shfl_sync(0xffffffffu, s, 31);

    if (lane == 0) cnt[w] = 0;
    __syncwarp();

    const bool flagged = (pv.w >= cut);   // chunk may hide a 5th candidate
    if (!flagged) {
        const float fv[4] = {pv.x, pv.y, pv.z, pv.w};
        const int   fi[4] = {pi.x, pi.y, pi.z, pi.w};
#pragma unroll
        for (int e = 0; e < 4; e++)
            if (fv[e] >= cut) {
                const int pos = atomicAdd(&cnt[w], 1);
                if (pos < CAPM) { cand_v[w][pos] = fv[e]; cand_i[w][pos] = fi[e]; }
            }
    }
    unsigned mask = __ballot_sync(0xffffffffu, flagged);
    while (mask) {                        // rare: rescan flagged chunks, MLP=16
        const int cc = __ffs(mask) - 1; mask &= mask - 1;
        const float* colp = qk + (size_t)b * NBLK * NCOLS + (size_t)(cc * CHUNK) * NCOLS + col;
        float vv[16];
#pragma unroll
        for (int u = 0; u < 16; u++)
            vv[u] = __ldg(colp + (size_t)(lane + u * 32) * NCOLS);
#pragma unroll
        for (int u = 0; u < 16; u++) {
            if (vv[u] >= cut) {
                const int pos = atomicAdd(&cnt[w], 1);
                if (pos < CAPM) { cand_v[w][pos] = vv[u]; cand_i[w][pos] = cc * CHUNK + lane + u * 32; }
            }
        }
    }
    __syncwarp();
    const int n = min(cnt[w], CAPM);
    for (int t = lane; t < CAPM; t += 32)
        if (t >= n) { cand_v[w][t] = NEG_INF; cand_i[w][t] = 0x7fffffff; }
    __syncwarp();

    // bitonic sort CAPM=64, desc by (v desc, idx asc)
    for (int k = 2; k <= CAPM; k <<= 1) {
        for (int jj = k >> 1; jj > 0; jj >>= 1) {
#pragma unroll
            for (int t = lane; t < CAPM; t += 32) {
                const int ixj = t ^ jj;
                if (ixj > t) {
                    float av = cand_v[w][t], bv = cand_v[w][ixj];
                    int   ai = cand_i[w][t], bi = cand_i[w][ixj];
                    const bool desc = ((t & k) == 0);
                    const bool sw = desc ? beats(bv, bi, av, ai) : beats(av, ai, bv, bi);
                    if (sw) { cand_v[w][t] = bv; cand_v[w][ixj] = av;
                              cand_i[w][t] = bi; cand_i[w][ixj] = ai; }
                }
            }
            __syncwarp();
        }
    }

    if (lane < KK) {
        out_val[cb * KK + lane] = cand_v[w][lane];
        out_idx[cb * KK + lane] = (float)cand_i[w][lane];
    }
    const int asc = wsort_int_asc(cand_i[w][lane]);
    g_sel[(size_t)cb * KSEL + lane] = asc;
}

// ---- attention: K resident in smem; PV = register-direct LDG pipeline -----
// grid (BB*NCOLS), block 256, dynamic smem ~68 KB -> 3 CTAs/SM
__global__ void __launch_bounds__(256) attention_k(
        const float* __restrict__ q_in, float* __restrict__ out) {
    extern __shared__ float sm[];
    float* kbuf = sm + SM_K;       // [32][512]
    float* q_s  = sm + SM_Q;       // [4][128]
    float* p_s  = sm + SM_P;       // [4][128]
    int*   sel  = (int*)(sm + SM_SEL);

    const int tid = threadIdx.x;
    const int b = blockIdx.x >> 10;
    const int colq = blockIdx.x & 1023;
    const int hr = colq >> 5, wr = colq & 31;
    const int cb = b * NCOLS + colq;

    if (tid < KSEL) sel[tid] = g_sel[(size_t)cb * KSEL + tid];
    {   // load + pre-scale q
        const int c = tid & 127, ii = tid >> 7;
        const size_t qoff = ((size_t)(b * DE + c) * HH + (2 * hr + ii)) * WW + 2 * wr;
        const float2 qv = *(const float2*)(q_in + qoff);
        const float sc = 0.08838834764831845f;   // 1/sqrt(128)
        q_s[(ii * 2 + 0) * 128 + c] = qv.x * sc;
        q_s[(ii * 2 + 1) * 128 + c] = qv.y * sc;
    }
    __syncthreads();

    // bulk-load ALL 32 K blocks (64 KB), one commit group
    const size_t gbase = (size_t)b * NBLK;
    {
#pragma unroll
        for (int i = 0; i < 16; i++) {
            const int f4 = i * 256 + tid;          // float4 idx into 32*128
            const int slot = f4 >> 7, off = f4 & 127;
            cp16(kbuf + (size_t)f4 * 4,
                 (const float4*)g_in_b + (gbase + sel[slot]) * 128 + off);
        }
        cp_commit();
        cp_wait<0>();
    }
    __syncthreads();

    // QK: sync-free, q in registers
    const int grp = tid >> 4, sub = tid & 15;
    const int ql = grp >> 2, pl = grp & 3;
    float qr[8];
#pragma unroll
    for (int k = 0; k < 8; k++) qr[k] = q_s[ql * 128 + sub + 16 * k];
#pragma unroll 4
    for (int s = 0; s < KSEL; s++) {
        const float* kv = kbuf + s * 512 + pl * 128;
        float part = 0.f;
#pragma unroll
        for (int k = 0; k < 8; k++) part += qr[k] * kv[sub + 16 * k];
        part += __shfl_xor_sync(0xffffffffu, part, 8);
        part += __shfl_xor_sync(0xffffffffu, part, 4);
        part += __shfl_xor_sync(0xffffffffu, part, 2);
        part += __shfl_xor_sync(0xffffffffu, part, 1);
        if (sub == 0) p_s[ql * 128 + s * 4 + pl] = part;
    }
    __syncthreads();

    // softmax over 128 keys; one warp per query
    {
        const int w = tid >> 5, lane = tid & 31;
        if (w < 4) {
            float x0 = p_s[w * 128 + lane],      x1 = p_s[w * 128 + lane + 32];
            float x2 = p_s[w * 128 + lane + 64], x3 = p_s[w * 128 + lane + 96];
            float m = fmaxf(fmaxf(x0, x1), fmaxf(x2, x3));
#pragma unroll
            for (int o = 16; o; o >>= 1) m = fmaxf(m, __shfl_xor_sync(0xffffffffu, m, o));
            float e0 = __expf(x0 - m), e1 = __expf(x1 - m);
            float e2 = __expf(x2 - m), e3 = __expf(x3 - m);
            float ssum = e0 + e1 + e2 + e3;
#pragma unroll
            for (int o = 16; o; o >>= 1) ssum += __shfl_xor_sync(0xffffffffu, ssum, o);
            const float inv = __fdividef(1.f, ssum);
            p_s[w * 128 + lane]      = e0 * inv; p_s[w * 128 + lane + 32] = e1 * inv;
            p_s[w * 128 + lane + 64] = e2 * inv; p_s[w * 128 + lane + 96] = e3 * inv;
        }
    }
    __syncthreads();

    // PV: register-direct LDG pipeline, depth 4, zero syncs / zero smem
    float a0 = 0.f, a1 = 0.f, a2 = 0.f, a3 = 0.f;
    float vr[4][4];
#pragma unroll
    for (int s = 0; s < 4; s++) {
        const float* src = g_out_b + (gbase + sel[s]) * 1024 + tid;
#pragma unroll
        for (int pos = 0; pos < 4; pos++) vr[s][pos] = __ldg(src + pos * 256);
    }
#pragma unroll 4
    for (int s = 0; s < KSEL; s++) {
        const int rs = s & 3;
        const float4 p0 = *(const float4*)(p_s + 0 * 128 + s * 4);
        const float4 p1 = *(const float4*)(p_s + 1 * 128 + s * 4);
        const float4 p2 = *(const float4*)(p_s + 2 * 128 + s * 4);
        const float4 p3 = *(const float4*)(p_s + 3 * 128 + s * 4);
        const float v0 = vr[rs][0], v1 = vr[rs][1], v2 = vr[rs][2], v3 = vr[rs][3];
        a0 += v0 * p0.x + v1 * p0.y + v2 * p0.z + v3 * p0.w;
        a1 += v0 * p1.x + v1 * p1.y + v2 * p1.z + v3 * p1.w;
        a2 += v0 * p2.x + v1 * p2.y + v2 * p2.z + v3 * p2.w;
        a3 += v0 * p3.x + v1 * p3.y + v2 * p3.z + v3 * p3.w;
        if (s + 4 < KSEL) {
            const float* src = g_out_b + (gbase + sel[s + 4]) * 1024 + tid;
#pragma unroll
            for (int pos = 0; pos < 4; pos++) vr[rs][pos] = __ldg(src + pos * 256);
        }
    }

    const size_t ob = ((size_t)(b * DO + tid) * HH + 2 * hr) * WW + 2 * wr;
    *(float2*)(out + ob)      = make_float2(a0, a1);
    *(float2*)(out + ob + WW) = make_float2(a2, a3);
}

// ---------------------------------------------------------------------------
extern "C" void kernel_launch(void* const* d_in, const int* in_sizes, int n_in,
                              void* d_out, int out_size) {
    const float* m_in   = (const float*)d_in[0];
    const float* m_out  = (const float*)d_in[1];
    const float* q_in   = (const float*)d_in[2];
    const float* qk_ref = (const float*)d_in[3];

    float* out_mem = (float*)d_out;
    float* out_idx = out_mem + (size_t)BB * DO * HH * WW;
    float* out_val = out_idx + (size_t)BB * NCOLS * KK;

    {   // blockify
        dim3 g1(HH, TT, BB * 1);
        blockify_k<DE, 1, true ><<<g1, 256>>>(m_in);
        dim3 g2(HH, TT, BB * 2);
        blockify_k<DO, 2, false><<<g2, 256>>>(m_out);
    }
    {   // selection
        dim3 gp(NCOLS / 256, NCHUNK, BB);
        topk_partial_k<<<gp, 256>>>(qk_ref);
        dim3 gm(NCOLS / 8, BB);
        topk_merge_k<<<gm, 256>>>(qk_ref, out_idx, out_val);
    }
    // attention
    cudaFuncSetAttribute(attention_k, cudaFuncAttributeMaxDynamicSharedMemorySize, SMEM_ATT_BYTES);
    attention_k<<<BB * NCOLS, 256, SMEM_ATT_BYTES>>>(q_in, out_mem);
}